// round 5
// baseline (speedup 1.0000x reference)
#include <cuda_runtime.h>
#include <cstdint>

// KAN layer as GEMM: out[1024,128] = A[1024,1024] @ B[1024,128] + bias
//   A[n, j*8+k] = Catmull-Rom basis weight (built in SMEM per n-tile)
//   B[j*8+k, o] = weights[o,j]*coeffs[o,j,k]  (built once, 512 KB, "group-of-4" layout)
//
// Main kernel: grid (256 n-tiles x 4 o-chunks) = 1024 blocks, 128 threads.
//   warp w (0..3) owns K-quarter; lane = o within 32-chunk.
//   Each thread: 4 rows x 256 k, f32x2 packed accumulation.
//   End: SMEM reduction of the 4 K-quarter partials, + bias, store.

#define D_IN  128
#define D_OUT 128
#define KNOTS 8
#define N_ROWS 1024
#define JK (D_IN * KNOTS)          // 1024
#define ROWS_PER_TILE 4
#define O_CHUNK 32
#define KSPLIT 4

typedef unsigned long long u64;

__device__ float g_WC[JK * D_OUT];  // [(jk/4)*512 + o*4 + (jk%4)]

__global__ void build_wc_kernel(const float* __restrict__ coeffs,
                                const float* __restrict__ weights) {
    int a = blockIdx.x * blockDim.x + threadIdx.x;   // 0 .. 131071
    int c  = a & 3;
    int o  = (a >> 2) & (D_OUT - 1);
    int g  = a >> 9;
    int jk = g * 4 + c;
    int j  = jk >> 3;
    int k  = jk & 7;
    g_WC[a] = weights[o * D_IN + j] * coeffs[(o * D_IN + j) * KNOTS + k];
}

#define FMA2(d, a, b, c) \
    asm("fma.rn.f32x2 %0, %1, %2, %3;" : "=l"(d) : "l"(a), "l"(b), "l"(c))
#define ADD2(d, a, b) \
    asm("add.rn.f32x2 %0, %1, %2;" : "=l"(d) : "l"(a), "l"(b))

__device__ __forceinline__ float pair_sum(u64 v) {
    float lo = __uint_as_float((unsigned)(v & 0xFFFFFFFFull));
    float hi = __uint_as_float((unsigned)(v >> 32));
    return lo + hi;
}

__global__ __launch_bounds__(128) void kan_main_kernel(
    const float* __restrict__ x,
    const float* __restrict__ bias,
    float* __restrict__ out) {
    __shared__ alignas(16) float a_s[ROWS_PER_TILE * JK];          // 16 KB
    __shared__ float red[(KSPLIT - 1) * ROWS_PER_TILE * O_CHUNK];  // 1.5 KB

    const int tid   = threadIdx.x;
    const int lane  = tid & 31;          // o within chunk
    const int kq    = tid >> 5;          // K-quarter 0..3 (= warp id)
    const int n0    = blockIdx.x * ROWS_PER_TILE;
    const int obase = blockIdx.y * O_CHUNK;
    const int o     = obase + lane;

    // ---- Stage 1: build basis tile A (4 rows x 1024), 4 evals per thread ----
    #pragma unroll
    for (int e = tid; e < ROWS_PER_TILE * D_IN; e += 128) {
        int nn = e >> 7;
        int j  = e & (D_IN - 1);
        float xv = x[(n0 + nn) * D_IN + j];
        float xc = fminf(fmaxf(xv, -1.0f), 1.0f);
        float t  = (xc + 1.0f) * 3.5f;               // h = 2/7
        int idx  = min((int)floorf(t), 6);
        float u  = t - (float)idx;
        float u2 = u * u, u3 = u2 * u;
        float b0 = 0.5f * (-u3 + 2.0f * u2 - u);
        float b1 = 0.5f * (3.0f * u3 - 5.0f * u2 + 2.0f);
        float b2 = 0.5f * (-3.0f * u3 + 4.0f * u2 + u);
        float b3 = 0.5f * (u3 - u2);
        int p0 = max(idx - 1, 0);
        int p3 = min(idx + 2, 7);
        float v[8];
        #pragma unroll
        for (int k = 0; k < 8; k++) {
            float s = 0.0f;
            s += (k == p0)      ? b0 : 0.0f;
            s += (k == idx)     ? b1 : 0.0f;
            s += (k == idx + 1) ? b2 : 0.0f;
            s += (k == p3)      ? b3 : 0.0f;
            v[k] = s;
        }
        float4* dst = (float4*)&a_s[nn * JK + j * 8];
        dst[0] = make_float4(v[0], v[1], v[2], v[3]);
        dst[1] = make_float4(v[4], v[5], v[6], v[7]);
    }
    __syncthreads();

    // ---- Stage 2: K-quarter GEMM, 4 rows/thread, f32x2 packed over k ----
    const int kg0 = kq * (JK / 4 / KSPLIT);          // 64 groups per quarter
    const ulonglong2* __restrict__ Bp = (const ulonglong2*)g_WC;
    const ulonglong2* __restrict__ Ap = (const ulonglong2*)a_s;

    u64 acc0[ROWS_PER_TILE], acc1[ROWS_PER_TILE];
    #pragma unroll
    for (int r = 0; r < ROWS_PER_TILE; r++) { acc0[r] = 0ull; acc1[r] = 0ull; }

    // Prefetch 2 groups ahead to cover L2 latency.
    ulonglong2 bf0 = Bp[(kg0 + 0) * D_OUT + o];
    ulonglong2 bf1 = Bp[(kg0 + 1) * D_OUT + o];

    #pragma unroll 4
    for (int g = 0; g < 64; g++) {
        ulonglong2 b = bf0;
        bf0 = bf1;
        int gn = (g + 2 < 64) ? (g + 2) : 63;
        bf1 = Bp[(kg0 + gn) * D_OUT + o];

        #pragma unroll
        for (int r = 0; r < ROWS_PER_TILE; r++) {
            ulonglong2 a = Ap[r * (JK / 4) + kg0 + g];   // broadcast LDS.128
            FMA2(acc0[r], a.x, b.x, acc0[r]);
            FMA2(acc1[r], a.y, b.y, acc1[r]);
        }
    }

    // Combine per-row partials to scalars.
    float s[ROWS_PER_TILE];
    #pragma unroll
    for (int r = 0; r < ROWS_PER_TILE; r++) {
        u64 t2;
        ADD2(t2, acc0[r], acc1[r]);
        s[r] = pair_sum(t2);
    }

    // ---- Stage 3: reduce the 4 K-quarter partials in SMEM ----
    if (kq > 0) {
        #pragma unroll
        for (int r = 0; r < ROWS_PER_TILE; r++)
            red[((kq - 1) * ROWS_PER_TILE + r) * O_CHUNK + lane] = s[r];
    }
    __syncthreads();
    if (kq == 0) {
        float bv = bias[o];
        #pragma unroll
        for (int r = 0; r < ROWS_PER_TILE; r++) {
            float v = s[r]
                    + red[(0 * ROWS_PER_TILE + r) * O_CHUNK + lane]
                    + red[(1 * ROWS_PER_TILE + r) * O_CHUNK + lane]
                    + red[(2 * ROWS_PER_TILE + r) * O_CHUNK + lane];
            out[(n0 + r) * D_OUT + o] = v + bv;
        }
    }
}

extern "C" void kernel_launch(void* const* d_in, const int* in_sizes, int n_in,
                              void* d_out, int out_size) {
    const float* x       = (const float*)d_in[0];   // [1024,128]
    const float* coeffs  = (const float*)d_in[1];   // [128,128,8]
    const float* weights = (const float*)d_in[2];   // [128,128]
    const float* bias    = (const float*)d_in[3];   // [128]
    float* out = (float*)d_out;                     // [1024,128]

    build_wc_kernel<<<(JK * D_OUT) / 512, 512>>>(coeffs, weights);
    dim3 grid(N_ROWS / ROWS_PER_TILE, D_OUT / O_CHUNK);   // (256, 4)
    kan_main_kernel<<<grid, 128>>>(x, bias, out);
}

// round 7
// speedup vs baseline: 1.5716x; 1.5716x over previous
#include <cuda_runtime.h>
#include <cstdint>

// KAN layer as GEMM: out[1024,128] = A[1024,1024] @ B[1024,128] + bias
//   A[n, j*8+k] = Catmull-Rom basis weight (built in SMEM per n-tile, value-duplicated pairs)
//   B[k, o]     = weights[o,j]*coeffs[o,j,k_local]  (plain row-major [k][o], built once)
//
// Main kernel: grid 256 (n-tiles of 4 rows), 256 threads (8 warps = K-eighths).
//   lane: pg = lane&15 -> 4 o-pairs [pg*4 .. pg*4+3] (floats pg*8..pg*8+7);
//         khalf = lane>>4 -> 64-k sub-slice of the warp's 128-k slice.
//   Thread tile: 4 rows x 8 o x 64 k, o-packed f32x2 accumulators.
//   Reduction: shfl_xor(16) fold, then SMEM (aliased onto A tile) across 8 warps.

#define D_IN  128
#define D_OUT 128
#define KNOTS 8
#define N_ROWS 1024
#define JK (D_IN * KNOTS)          // 1024 = K of the GEMM
#define ROWS 4

typedef unsigned long long u64;

__device__ float g_WC2[JK * D_OUT];   // [k][o] row-major

__global__ void build_wc_kernel(const float* __restrict__ coeffs,
                                const float* __restrict__ weights) {
    int f = blockIdx.x * blockDim.x + threadIdx.x;   // 0 .. 131071
    int o  = f & (D_OUT - 1);
    int k  = f >> 7;
    int j  = k >> 3;
    int kk = k & 7;
    g_WC2[f] = weights[o * D_IN + j] * coeffs[(o * D_IN + j) * KNOTS + kk];
}

#define FMA2(d, a, b, c) \
    asm("fma.rn.f32x2 %0, %1, %2, %3;" : "=l"(d) : "l"(a), "l"(b), "l"(c))
#define ADD2(d, a, b) \
    asm("add.rn.f32x2 %0, %1, %2;" : "=l"(d) : "l"(a), "l"(b))

__global__ __launch_bounds__(256, 2) void kan_main_kernel(
    const float* __restrict__ x,
    const float* __restrict__ bias,
    float* __restrict__ out) {
    // A tile, value-duplicated: a2[r][k] = {A[r][k], A[r][k]} as u64. 32 KB.
    // After the mainloop it is re-used as the cross-warp reduction buffer.
    __shared__ alignas(16) u64 a2_s[ROWS * JK];

    const int tid   = threadIdx.x;
    const int lane  = tid & 31;
    const int kq    = tid >> 5;          // warp = K-eighth
    const int pg    = lane & 15;         // o-pair group: pairs pg*4 .. pg*4+3
    const int khalf = lane >> 4;         // which 64-k half of the warp's slice
    const int n0    = blockIdx.x * ROWS;

    // ---- Stage 1: build basis tile (4 rows x 128 j), 2 evals/thread ----
    #pragma unroll
    for (int e = tid; e < ROWS * D_IN; e += 256) {
        int nn = e >> 7;
        int j  = e & (D_IN - 1);
        float xv = x[(n0 + nn) * D_IN + j];
        float xc = fminf(fmaxf(xv, -1.0f), 1.0f);
        float t  = (xc + 1.0f) * 3.5f;               // h = 2/7
        int idx  = min((int)floorf(t), 6);
        float u  = t - (float)idx;
        float u2 = u * u, u3 = u2 * u;
        float b0 = 0.5f * (-u3 + 2.0f * u2 - u);
        float b1 = 0.5f * (3.0f * u3 - 5.0f * u2 + 2.0f);
        float b2 = 0.5f * (-3.0f * u3 + 4.0f * u2 + u);
        float b3 = 0.5f * (u3 - u2);
        int p0 = max(idx - 1, 0);
        int p3 = min(idx + 2, 7);
        float v[8];
        #pragma unroll
        for (int k = 0; k < 8; k++) {
            float s = 0.0f;
            s += (k == p0)      ? b0 : 0.0f;
            s += (k == idx)     ? b1 : 0.0f;
            s += (k == idx + 1) ? b2 : 0.0f;
            s += (k == p3)      ? b3 : 0.0f;
            v[k] = s;
        }
        float4* dst = (float4*)&a2_s[nn * JK + j * 8];   // 8 u64 = 4 float4 (dup pairs)
        dst[0] = make_float4(v[0], v[0], v[1], v[1]);
        dst[1] = make_float4(v[2], v[2], v[3], v[3]);
        dst[2] = make_float4(v[4], v[4], v[5], v[5]);
        dst[3] = make_float4(v[6], v[6], v[7], v[7]);
    }
    __syncthreads();

    // ---- Stage 2: mainloop. 32 iterations of 2 k each ----
    const ulonglong2* __restrict__ Bp = (const ulonglong2*)g_WC2;  // 4 floats = 2 o-pairs each
    const ulonglong2* __restrict__ Ap = (const ulonglong2*)a2_s;   // {a,a},{a',a'}

    const int k0base = kq * 128 + khalf * 64;       // this lane's first k
    const int abase  = k0base >> 1;                 // ulonglong2 index within a row
    // B row = 128 floats = 32 ulonglong2. This thread's 8 floats start at
    // float pg*8 -> ulonglong2 offset pg*2 (FIX: was pg*8 in R6).
    int bi = k0base * 32 + pg * 2;
    const int bi0 = bi;

    u64 acc[ROWS][4];
    #pragma unroll
    for (int r = 0; r < ROWS; r++)
        #pragma unroll
        for (int p = 0; p < 4; p++) acc[r][p] = 0ull;

    // prefetch iteration 0:  (k0: pairs 0-3), (k0+1: pairs 0-3)
    ulonglong2 c00 = Bp[bi];      ulonglong2 c01 = Bp[bi + 1];
    ulonglong2 c10 = Bp[bi + 32]; ulonglong2 c11 = Bp[bi + 33];

    #pragma unroll 4
    for (int t2 = 0; t2 < 32; t2++) {
        bi += 64;
        int bn = (t2 < 31) ? bi : bi0;              // clamp: harmless reload
        ulonglong2 n00 = Bp[bn];      ulonglong2 n01 = Bp[bn + 1];
        ulonglong2 n10 = Bp[bn + 32]; ulonglong2 n11 = Bp[bn + 33];

        #pragma unroll
        for (int r = 0; r < ROWS; r++) {
            ulonglong2 A01 = Ap[r * (JK / 2) + abase + t2];  // {a_k,a_k},{a_k1,a_k1}
            FMA2(acc[r][0], A01.x, c00.x, acc[r][0]);
            FMA2(acc[r][1], A01.x, c00.y, acc[r][1]);
            FMA2(acc[r][2], A01.x, c01.x, acc[r][2]);
            FMA2(acc[r][3], A01.x, c01.y, acc[r][3]);
            FMA2(acc[r][0], A01.y, c10.x, acc[r][0]);
            FMA2(acc[r][1], A01.y, c10.y, acc[r][1]);
            FMA2(acc[r][2], A01.y, c11.x, acc[r][2]);
            FMA2(acc[r][3], A01.y, c11.y, acc[r][3]);
        }
        c00 = n00; c01 = n01; c10 = n10; c11 = n11;
    }

    // ---- Fold the two k-halves within the warp (lanes L <-> L+16) ----
    #pragma unroll
    for (int r = 0; r < ROWS; r++)
        #pragma unroll
        for (int p = 0; p < 4; p++) {
            u64 other = __shfl_xor_sync(0xffffffffu, acc[r][p], 16);
            ADD2(acc[r][p], acc[r][p], other);
        }

    // ---- Cross-warp reduction in SMEM (aliases a2_s after sync) ----
    __syncthreads();                 // everyone done reading a2_s
    u64* red = a2_s;                 // red[(kq*ROWS + r)*64 + pair]
    if (khalf == 0) {
        #pragma unroll
        for (int r = 0; r < ROWS; r++)
            #pragma unroll
            for (int p = 0; p < 4; p++)
                red[(kq * ROWS + r) * 64 + pg * 4 + p] = acc[r][p];
    }
    __syncthreads();

    // ---- Epilogue: 256 threads x 1 output-pair ----
    {
        int r  = tid >> 6;           // 0..3
        int pr = tid & 63;           // o-pair 0..63
        u64 s = red[(0 * ROWS + r) * 64 + pr];
        #pragma unroll
        for (int w = 1; w < 8; w++)
            ADD2(s, s, red[(w * ROWS + r) * 64 + pr]);
        float2 bv = ((const float2*)bias)[pr];
        u64 bp;
        asm("mov.b64 %0, {%1, %2};" : "=l"(bp) : "r"(__float_as_uint(bv.x)), "r"(__float_as_uint(bv.y)));
        ADD2(s, s, bp);
        unsigned lo = (unsigned)(s & 0xFFFFFFFFull);
        unsigned hi = (unsigned)(s >> 32);
        ((float2*)out)[(n0 + r) * (D_OUT / 2) + pr] =
            make_float2(__uint_as_float(lo), __uint_as_float(hi));
    }
}

extern "C" void kernel_launch(void* const* d_in, const int* in_sizes, int n_in,
                              void* d_out, int out_size) {
    const float* x       = (const float*)d_in[0];   // [1024,128]
    const float* coeffs  = (const float*)d_in[1];   // [128,128,8]
    const float* weights = (const float*)d_in[2];   // [128,128]
    const float* bias    = (const float*)d_in[3];   // [128]
    float* out = (float*)d_out;                     // [1024,128]

    build_wc_kernel<<<(JK * D_OUT) / 256, 256>>>(coeffs, weights);
    kan_main_kernel<<<N_ROWS / ROWS, 256>>>(x, bias, out);
}